// round 8
// baseline (speedup 1.0000x reference)
#include <cuda_runtime.h>
#include <cstdint>

#define N_DIM 8192
#define K_DIM 4096
#define M_DIM 4096

// unified 128x128 output tiles
#define BT 128
#define ROW_TILES (N_DIM / BT)       // 64
#define COL_TILES (M_DIM / BT)       // 32
#define N_TILES   (ROW_TILES * COL_TILES)  // 2048
#define NSM 148
#define T_IMMA 1036                  // tiles given to the IMMA CTAs (7 * 148)

#define BK 64
#define K_TILES (K_DIM / BK)         // 64
#define STAGES 3
#define THREADS 256
#define SROW 132

// Scratch (device globals: no allocation allowed)
__device__ int8_t g_qx[(size_t)N_DIM * K_DIM];
__device__ int8_t g_qw[(size_t)M_DIM * K_DIM];
__device__ unsigned int g_amax_bits[2];

// ---------------------------------------------------------------- helpers
__device__ __forceinline__ uint32_t smem_u32(const void* p) {
    uint32_t a;
    asm("{ .reg .u64 t; cvta.to.shared.u64 t, %1; cvt.u32.u64 %0, t; }" : "=r"(a) : "l"(p));
    return a;
}
__device__ __forceinline__ uint32_t swz(uint32_t off) {   // 64B-row XOR swizzle
    return off ^ ((off >> 3) & 0x30);
}
__device__ __forceinline__ void cp16(uint32_t dst, const void* src) {
    asm volatile("cp.async.cg.shared.global [%0], [%1], 16;" :: "r"(dst), "l"(src));
}
#define CP_COMMIT() asm volatile("cp.async.commit_group;" ::: "memory")

__device__ __forceinline__ void ldmx4(uint32_t* r, uint32_t addr) {
    asm volatile("ldmatrix.sync.aligned.m8n8.x4.shared.b16 {%0,%1,%2,%3}, [%4];"
                 : "=r"(r[0]), "=r"(r[1]), "=r"(r[2]), "=r"(r[3]) : "r"(addr));
}
__device__ __forceinline__ void imma(int* c, const uint32_t* a, uint32_t b0, uint32_t b1) {
    asm volatile(
        "mma.sync.aligned.m16n8k32.row.col.s32.s8.s8.s32 "
        "{%0,%1,%2,%3}, {%4,%5,%6,%7}, {%8,%9}, {%0,%1,%2,%3};"
        : "+r"(c[0]), "+r"(c[1]), "+r"(c[2]), "+r"(c[3])
        : "r"(a[0]), "r"(a[1]), "r"(a[2]), "r"(a[3]), "r"(b0), "r"(b1));
}

// ---------------------------------------------------------------- preproc
__global__ void init_kernel() { g_amax_bits[0] = 0u; g_amax_bits[1] = 0u; }

__global__ void amax_kernel(const float* __restrict__ in, long long n4, int slot) {
    float m = 0.0f;
    long long i0 = (long long)blockIdx.x * blockDim.x + threadIdx.x;
    long long stride = (long long)gridDim.x * blockDim.x;
    const float4* in4 = (const float4*)in;
    for (long long i = i0; i < n4; i += stride) {
        float4 v = in4[i];
        m = fmaxf(m, fmaxf(fmaxf(fabsf(v.x), fabsf(v.y)),
                           fmaxf(fabsf(v.z), fabsf(v.w))));
    }
#pragma unroll
    for (int o = 16; o; o >>= 1) m = fmaxf(m, __shfl_xor_sync(0xffffffffu, m, o));
    __shared__ float sm[32];
    int lane = threadIdx.x & 31, wid = threadIdx.x >> 5;
    if (lane == 0) sm[wid] = m;
    __syncthreads();
    if (wid == 0) {
        m = (lane < (int)(blockDim.x >> 5)) ? sm[lane] : 0.0f;
#pragma unroll
        for (int o = 16; o; o >>= 1) m = fmaxf(m, __shfl_xor_sync(0xffffffffu, m, o));
        if (lane == 0) atomicMax(&g_amax_bits[slot], __float_as_uint(m));
    }
}

__global__ void quant_kernel(const float* __restrict__ in, int8_t* __restrict__ out,
                             long long n4, int slot) {
    float amax = __uint_as_float(g_amax_bits[slot]);
    float scale = 127.0f / amax;
    long long i0 = (long long)blockIdx.x * blockDim.x + threadIdx.x;
    long long stride = (long long)gridDim.x * blockDim.x;
    const float4* in4 = (const float4*)in;
    char4* out4 = (char4*)out;
    for (long long i = i0; i < n4; i += stride) {
        float4 v = in4[i];
        char4 q;
        q.x = (signed char)__float2int_rn(fminf(fmaxf(v.x * scale, -127.0f), 127.0f));
        q.y = (signed char)__float2int_rn(fminf(fmaxf(v.y * scale, -127.0f), 127.0f));
        q.z = (signed char)__float2int_rn(fminf(fmaxf(v.z * scale, -127.0f), 127.0f));
        q.w = (signed char)__float2int_rn(fminf(fmaxf(v.w * scale, -127.0f), 127.0f));
        out4[i] = q;
    }
}

// ---------------------------------------------------------------- fused GEMM
union SmemU {
    struct { int8_t A[STAGES][BT * BK]; int8_t B[STAGES][BT * BK]; } im;  // 49152 B
    struct { int As[16 * SROW]; int Bs[16 * SROW]; } dp;                  // 16896 B
};

// ---- IMMA tile: 128x128 out, 8 warps (4M x 2N), warp tile 32x64
__device__ __forceinline__ void imma_tile(
    SmemU* sm, const int8_t* __restrict__ qx, const int8_t* __restrict__ qw,
    const float* __restrict__ bias, float* __restrict__ out,
    int row0, int col0, float dq,
    const uint32_t offA[2][2], const uint32_t offB[4][2]) {

    const int tid = threadIdx.x, wid = tid >> 5, lane = tid & 31;
    const int wM = wid & 3, wN = wid >> 2;
    const uint32_t sA0 = smem_u32(sm->im.A);
    const uint32_t sB0 = smem_u32(sm->im.B);
    const int8_t* aG = qx + (size_t)row0 * K_DIM;
    const int8_t* bG = qw + (size_t)col0 * K_DIM;

    int acc[2][8][4];
#pragma unroll
    for (int i = 0; i < 2; ++i)
#pragma unroll
        for (int j = 0; j < 8; ++j)
#pragma unroll
            for (int k = 0; k < 4; ++k) acc[i][j][k] = 0;

    auto load_stage = [&](int s, int kt) {
        const int kb = kt * BK;
#pragma unroll
        for (int p = 0; p < 2; ++p) {
            int i = p * THREADS + tid;
            int r = i >> 2, c = i & 3;
            uint32_t so = swz((uint32_t)(r * BK + c * 16));
            cp16(sA0 + s * (BT * BK) + so, aG + (size_t)r * K_DIM + kb + c * 16);
            cp16(sB0 + s * (BT * BK) + so, bG + (size_t)r * K_DIM + kb + c * 16);
        }
        CP_COMMIT();
    };

    load_stage(0, 0);
    load_stage(1, 1);

    for (int kt = 0; kt < K_TILES; ++kt) {
        const int s = kt % STAGES;
        if (kt + 2 < K_TILES) {
            asm volatile("cp.async.wait_group %0;" :: "n"(1) : "memory");
        } else {
            asm volatile("cp.async.wait_group %0;" :: "n"(0) : "memory");
        }
        __syncthreads();
        if (kt + 2 < K_TILES) load_stage((kt + 2) % STAGES, kt + 2);

        const uint32_t aBase = sA0 + s * (BT * BK);
        const uint32_t bBase = sB0 + s * (BT * BK);
#pragma unroll
        for (int kc = 0; kc < 2; ++kc) {
            uint32_t a[2][4];
            ldmx4(a[0], aBase + offA[0][kc]);
            ldmx4(a[1], aBase + offA[1][kc]);
#pragma unroll
            for (int p = 0; p < 4; ++p) {
                uint32_t b[4];
                ldmx4(b, bBase + offB[p][kc]);
                imma(acc[0][2 * p + 0], a[0], b[0], b[1]);
                imma(acc[1][2 * p + 0], a[1], b[0], b[1]);
                imma(acc[0][2 * p + 1], a[0], b[2], b[3]);
                imma(acc[1][2 * p + 1], a[1], b[2], b[3]);
            }
        }
    }
    __syncthreads();   // smem safe for next tile's loads

    const int g = lane >> 2, tig = lane & 3;
    const int rbase = row0 + wM * 32;
    const int cbase = col0 + wN * 64;
#pragma unroll
    for (int ma = 0; ma < 2; ++ma) {
#pragma unroll
        for (int nb = 0; nb < 8; ++nb) {
            int r = rbase + ma * 16 + g;
            int c = cbase + nb * 8 + tig * 2;
            float2 bv = *(const float2*)(bias + c);
            float2 v0, v1;
            v0.x = (float)acc[ma][nb][0] * dq + bv.x;
            v0.y = (float)acc[ma][nb][1] * dq + bv.y;
            v1.x = (float)acc[ma][nb][2] * dq + bv.x;
            v1.y = (float)acc[ma][nb][3] * dq + bv.y;
            *(float2*)(out + (size_t)r * M_DIM + c) = v0;
            *(float2*)(out + (size_t)(r + 8) * M_DIM + c) = v1;
        }
    }
}

// ---- dp4a tile: 128x128 out, 256 threads, 8x8 per thread, reg-prefetch
__device__ __forceinline__ void dp4a_tile(
    SmemU* sm, const int8_t* __restrict__ qx, const int8_t* __restrict__ qw,
    const float* __restrict__ bias, float* __restrict__ out,
    int row0, int col0, float dq) {

    int* As = sm->dp.As;
    int* Bs = sm->dp.Bs;
    const int tid = threadIdx.x;
    const int tx = tid & 15, ty = tid >> 4;

    int acc[8][8];
#pragma unroll
    for (int i = 0; i < 8; ++i)
#pragma unroll
        for (int j = 0; j < 8; ++j) acc[i][j] = 0;

    const int rA = tid >> 2, qA = tid & 3;
    const int rB = (tid + 256) >> 2, qB = (tid + 256) & 3;
    const int8_t* aG = qx + (size_t)row0 * K_DIM;
    const int8_t* bG = qw + (size_t)col0 * K_DIM;

    uint4 a_v0, a_v1, b_v0, b_v1;
    auto ldg = [&](int kt) {
        const int kb = kt * BK;
        a_v0 = *(const uint4*)(aG + (size_t)rA * K_DIM + kb + qA * 16);
        a_v1 = *(const uint4*)(aG + (size_t)rB * K_DIM + kb + qB * 16);
        b_v0 = *(const uint4*)(bG + (size_t)rA * K_DIM + kb + qA * 16);
        b_v1 = *(const uint4*)(bG + (size_t)rB * K_DIM + kb + qB * 16);
    };
    ldg(0);

    for (int kt = 0; kt < K_TILES; ++kt) {
        __syncthreads();
        {
            int wb = qA * 4;
            As[(wb + 0) * SROW + rA] = a_v0.x; As[(wb + 1) * SROW + rA] = a_v0.y;
            As[(wb + 2) * SROW + rA] = a_v0.z; As[(wb + 3) * SROW + rA] = a_v0.w;
            Bs[(wb + 0) * SROW + rA] = b_v0.x; Bs[(wb + 1) * SROW + rA] = b_v0.y;
            Bs[(wb + 2) * SROW + rA] = b_v0.z; Bs[(wb + 3) * SROW + rA] = b_v0.w;
        }
        {
            int wb = qB * 4;
            As[(wb + 0) * SROW + rB] = a_v1.x; As[(wb + 1) * SROW + rB] = a_v1.y;
            As[(wb + 2) * SROW + rB] = a_v1.z; As[(wb + 3) * SROW + rB] = a_v1.w;
            Bs[(wb + 0) * SROW + rB] = b_v1.x; Bs[(wb + 1) * SROW + rB] = b_v1.y;
            Bs[(wb + 2) * SROW + rB] = b_v1.z; Bs[(wb + 3) * SROW + rB] = b_v1.w;
        }
        __syncthreads();

        if (kt + 1 < K_TILES) ldg(kt + 1);   // prefetch overlaps compute

        const int4* As4 = (const int4*)As;
        const int4* Bs4 = (const int4*)Bs;
#pragma unroll 4
        for (int kk = 0; kk < 16; ++kk) {
            int4 a0 = As4[kk * 33 + ty];
            int4 a1 = As4[kk * 33 + 16 + ty];
            int4 b0 = Bs4[kk * 33 + tx];
            int4 b1 = Bs4[kk * 33 + 16 + tx];
            int a[8] = {a0.x, a0.y, a0.z, a0.w, a1.x, a1.y, a1.z, a1.w};
            int b[8] = {b0.x, b0.y, b0.z, b0.w, b1.x, b1.y, b1.z, b1.w};
#pragma unroll
            for (int i = 0; i < 8; ++i)
#pragma unroll
                for (int j = 0; j < 8; ++j)
                    acc[i][j] = __dp4a(a[i], b[j], acc[i][j]);
        }
    }
    __syncthreads();

#pragma unroll
    for (int i = 0; i < 8; ++i) {
        int row = row0 + ty * 4 + (i & 3) + (i >> 2) * 64;
#pragma unroll
        for (int jg = 0; jg < 2; ++jg) {
            int col = col0 + tx * 4 + jg * 64;
            float4 bv = *(const float4*)(bias + col);
            float4 o;
            o.x = (float)acc[i][jg * 4 + 0] * dq + bv.x;
            o.y = (float)acc[i][jg * 4 + 1] * dq + bv.y;
            o.z = (float)acc[i][jg * 4 + 2] * dq + bv.z;
            o.w = (float)acc[i][jg * 4 + 3] * dq + bv.w;
            *(float4*)(out + (size_t)row * M_DIM + col) = o;
        }
    }
}

// ---- persistent fused kernel: bid<148 -> IMMA CTA, else dp4a CTA.
// Classic placement maps bid and bid+148 to the same SM, so each SM hosts
// one CTA of each type -> ALU pipe (dp4a) and tensor path (IMMA) run
// concurrently.
__global__ __launch_bounds__(THREADS, 2)
void gemm_fused(const int8_t* __restrict__ qx, const int8_t* __restrict__ qw,
                const float* __restrict__ bias, float* __restrict__ out) {
    __shared__ __align__(1024) SmemU sm;
    const int bid = blockIdx.x;
    const float dq = (__uint_as_float(g_amax_bits[0]) * __uint_as_float(g_amax_bits[1]))
                     / (127.0f * 127.0f);

    if (bid < NSM) {
        // precompute ldmatrix offsets once
        const int tid = threadIdx.x, wid = tid >> 5, lane = tid & 31;
        const int wM = wid & 3, wN = wid >> 2;
        uint32_t offA[2][2], offB[4][2];
#pragma unroll
        for (int ma = 0; ma < 2; ++ma)
#pragma unroll
            for (int kc = 0; kc < 2; ++kc) {
                int r = wM * 32 + ma * 16 + (lane & 15);
                int ch = kc * 2 + (lane >> 4);
                offA[ma][kc] = swz((uint32_t)(r * BK + ch * 16));
            }
#pragma unroll
        for (int p = 0; p < 4; ++p)
#pragma unroll
            for (int kc = 0; kc < 2; ++kc) {
                int c = wN * 64 + p * 16 + ((lane >> 4) & 1) * 8 + (lane & 7);
                int ch = kc * 2 + ((lane >> 3) & 1);
                offB[p][kc] = swz((uint32_t)(c * BK + ch * 16));
            }
        for (int t = bid; t < T_IMMA; t += NSM) {
            int row0 = (t & (ROW_TILES - 1)) * BT;
            int col0 = (t >> 6) * BT;
            imma_tile(&sm, qx, qw, bias, out, row0, col0, dq, offA, offB);
        }
    } else {
        for (int t = T_IMMA + (bid - NSM); t < N_TILES; t += NSM) {
            int row0 = (t & (ROW_TILES - 1)) * BT;
            int col0 = (t >> 6) * BT;
            dp4a_tile(&sm, qx, qw, bias, out, row0, col0, dq);
        }
    }
}

// ---------------------------------------------------------------- launch
extern "C" void kernel_launch(void* const* d_in, const int* in_sizes, int n_in,
                              void* d_out, int out_size) {
    const float* x = (const float*)d_in[0];
    const float* w = (const float*)d_in[1];
    const float* bias = (const float*)d_in[2];
    float* out = (float*)d_out;

    int8_t* qx;
    int8_t* qw;
    cudaGetSymbolAddress((void**)&qx, g_qx);
    cudaGetSymbolAddress((void**)&qw, g_qw);

    const long long nx4 = (long long)N_DIM * K_DIM / 4;
    const long long nw4 = (long long)M_DIM * K_DIM / 4;

    init_kernel<<<1, 32>>>();
    amax_kernel<<<1024, 256>>>(x, nx4, 0);
    amax_kernel<<<1024, 256>>>(w, nw4, 1);
    quant_kernel<<<1024, 256>>>(x, qx, nx4, 0);
    quant_kernel<<<1024, 256>>>(w, qw, nw4, 1);

    gemm_fused<<<2 * NSM, THREADS>>>(qx, qw, bias, out);
}

// round 9
// speedup vs baseline: 2.3488x; 2.3488x over previous
#include <cuda_runtime.h>
#include <cuda_fp16.h>
#include <cstdint>

#define N_DIM 8192
#define K_DIM 4096
#define M_DIM 4096

#define BM 128
#define BN 256
#define BKH 32                         // K elements (halves) per stage
#define ROWB 64                        // bytes per smem row (32 halves)
#define STAGES 3
#define K_TILES (K_DIM / BKH)          // 128
#define THREADS 256

#define STG_A (BM * ROWB)              // 8192 B
#define STG_B (BN * ROWB)              // 16384 B
#define SM_B_OFF (STAGES * STG_A)      // 24576
#define SMEM_TOTAL (STAGES * (STG_A + STG_B))  // 73728

// Scratch (device globals: no allocation allowed)
__device__ __half g_qxh[(size_t)N_DIM * K_DIM];   // quantized x as exact-int fp16
__device__ __half g_qwh[(size_t)M_DIM * K_DIM];
__device__ unsigned int g_amax_bits[2];

// ---------------------------------------------------------------- helpers
__device__ __forceinline__ uint32_t smem_u32(const void* p) {
    uint32_t a;
    asm("{ .reg .u64 t; cvta.to.shared.u64 t, %1; cvt.u32.u64 %0, t; }" : "=r"(a) : "l"(p));
    return a;
}
__device__ __forceinline__ uint32_t swz(uint32_t off) {   // 64B-row XOR swizzle
    return off ^ ((off >> 3) & 0x30);
}
__device__ __forceinline__ void cp16(uint32_t dst, const void* src) {
    asm volatile("cp.async.cg.shared.global [%0], [%1], 16;" :: "r"(dst), "l"(src));
}
#define CP_COMMIT() asm volatile("cp.async.commit_group;" ::: "memory")

__device__ __forceinline__ void ldmx4(uint32_t* r, uint32_t addr) {
    asm volatile("ldmatrix.sync.aligned.m8n8.x4.shared.b16 {%0,%1,%2,%3}, [%4];"
                 : "=r"(r[0]), "=r"(r[1]), "=r"(r[2]), "=r"(r[3]) : "r"(addr));
}
__device__ __forceinline__ void hmma(float* c, const uint32_t* a, uint32_t b0, uint32_t b1) {
    asm volatile(
        "mma.sync.aligned.m16n8k16.row.col.f32.f16.f16.f32 "
        "{%0,%1,%2,%3}, {%4,%5,%6,%7}, {%8,%9}, {%0,%1,%2,%3};"
        : "+f"(c[0]), "+f"(c[1]), "+f"(c[2]), "+f"(c[3])
        : "r"(a[0]), "r"(a[1]), "r"(a[2]), "r"(a[3]), "r"(b0), "r"(b1));
}

// ---------------------------------------------------------------- preproc
__global__ void init_kernel() { g_amax_bits[0] = 0u; g_amax_bits[1] = 0u; }

__global__ void amax_kernel(const float* __restrict__ in, long long n4, int slot) {
    float m = 0.0f;
    long long i0 = (long long)blockIdx.x * blockDim.x + threadIdx.x;
    long long stride = (long long)gridDim.x * blockDim.x;
    const float4* in4 = (const float4*)in;
    for (long long i = i0; i < n4; i += stride) {
        float4 v = in4[i];
        m = fmaxf(m, fmaxf(fmaxf(fabsf(v.x), fabsf(v.y)),
                           fmaxf(fabsf(v.z), fabsf(v.w))));
    }
#pragma unroll
    for (int o = 16; o; o >>= 1) m = fmaxf(m, __shfl_xor_sync(0xffffffffu, m, o));
    __shared__ float sm[32];
    int lane = threadIdx.x & 31, wid = threadIdx.x >> 5;
    if (lane == 0) sm[wid] = m;
    __syncthreads();
    if (wid == 0) {
        m = (lane < (int)(blockDim.x >> 5)) ? sm[lane] : 0.0f;
#pragma unroll
        for (int o = 16; o; o >>= 1) m = fmaxf(m, __shfl_xor_sync(0xffffffffu, m, o));
        if (lane == 0) atomicMax(&g_amax_bits[slot], __float_as_uint(m));
    }
}

// quantize both tensors in one launch (grid.y: 0 = x, 1 = w); rn-to-even,
// clip +-127, store as exact-integer fp16.
__global__ void quant_both_kernel(const float* __restrict__ x, const float* __restrict__ w) {
    const int which = blockIdx.y;
    const float* in = which ? w : x;
    __half* out = which ? g_qwh : g_qxh;
    const long long n4 = which ? (long long)M_DIM * K_DIM / 4
                               : (long long)N_DIM * K_DIM / 4;
    float amax = __uint_as_float(g_amax_bits[which]);
    float scale = 127.0f / amax;
    long long i0 = (long long)blockIdx.x * blockDim.x + threadIdx.x;
    long long stride = (long long)gridDim.x * blockDim.x;
    const float4* in4 = (const float4*)in;
    __half2* out2 = (__half2*)out;
    for (long long i = i0; i < n4; i += stride) {
        float4 v = in4[i];
        float q0 = (float)__float2int_rn(fminf(fmaxf(v.x * scale, -127.0f), 127.0f));
        float q1 = (float)__float2int_rn(fminf(fmaxf(v.y * scale, -127.0f), 127.0f));
        float q2 = (float)__float2int_rn(fminf(fmaxf(v.z * scale, -127.0f), 127.0f));
        float q3 = (float)__float2int_rn(fminf(fmaxf(v.w * scale, -127.0f), 127.0f));
        out2[2 * i + 0] = __floats2half2_rn(q0, q1);
        out2[2 * i + 1] = __floats2half2_rn(q2, q3);
    }
}

// ---------------------------------------------------------------- HMMA GEMM
// out[N_DIM, M_DIM] = qxh[N,K] * qwh[M,K]^T (f32 acc) * dq + bias.
// Block 128x256, BK=32 halves (64B rows). 8 warps: wM = wid&3, wN = wid>>2.
// Warp tile 32(M) x 128(N): 2 matoms x 16 natoms of m16n8k16.
__global__ __launch_bounds__(THREADS, 1)
void gemm_hmma(const __half* __restrict__ qx, const __half* __restrict__ qw,
               const float* __restrict__ bias, float* __restrict__ out) {
    extern __shared__ char smem[];
    const uint32_t sA0 = smem_u32(smem);
    const uint32_t sB0 = sA0 + SM_B_OFF;

    const int tid = threadIdx.x, wid = tid >> 5, lane = tid & 31;
    const int wM = wid & 3, wN = wid >> 2;
    const int row0 = blockIdx.y * BM;   // N_DIM
    const int col0 = blockIdx.x * BN;   // M_DIM

    const char* aG = (const char*)(qx + (size_t)row0 * K_DIM);
    const char* bG = (const char*)(qw + (size_t)col0 * K_DIM);

    float acc[2][16][4];
#pragma unroll
    for (int i = 0; i < 2; ++i)
#pragma unroll
        for (int j = 0; j < 16; ++j)
#pragma unroll
            for (int k = 0; k < 4; ++k) acc[i][j][k] = 0.0f;

    // stage loader: A 128 rows x 4 chunks (512 cp16), B 256 x 4 (1024 cp16)
    auto load_stage = [&](int s, int kt) {
        const size_t kb = (size_t)kt * ROWB;           // byte offset along K
#pragma unroll
        for (int p = 0; p < 2; ++p) {
            int i = p * THREADS + tid;
            int r = i >> 2, c = i & 3;
            uint32_t so = swz((uint32_t)(r * ROWB + c * 16));
            cp16(sA0 + s * STG_A + so, aG + (size_t)r * (K_DIM * 2) + kb + c * 16);
        }
#pragma unroll
        for (int p = 0; p < 4; ++p) {
            int i = p * THREADS + tid;
            int r = i >> 2, c = i & 3;
            uint32_t so = swz((uint32_t)(r * ROWB + c * 16));
            cp16(sB0 + s * STG_B + so, bG + (size_t)r * (K_DIM * 2) + kb + c * 16);
        }
        CP_COMMIT();
    };

    // ldmatrix offsets (validated geometry from the int8 kernel; 64B rows):
    // A (matom ma, katom kc): row = wM*32 + ma*16 + (lane&15), chunk = kc*2 + (lane>>4)
    uint32_t offA[2][2];
#pragma unroll
    for (int ma = 0; ma < 2; ++ma)
#pragma unroll
        for (int kc = 0; kc < 2; ++kc) {
            int r = wM * 32 + ma * 16 + (lane & 15);
            int ch = kc * 2 + (lane >> 4);
            offA[ma][kc] = swz((uint32_t)(r * ROWB + ch * 16));
        }
    // B (npair p: n16 block, katom kc): row n = wN*128 + p*16 + ((lane>>4)&1)*8 + (lane&7)
    //                                   chunk = kc*2 + ((lane>>3)&1)
    uint32_t offB[8][2];
#pragma unroll
    for (int p = 0; p < 8; ++p)
#pragma unroll
        for (int kc = 0; kc < 2; ++kc) {
            int n = wN * 128 + p * 16 + ((lane >> 4) & 1) * 8 + (lane & 7);
            int ch = kc * 2 + ((lane >> 3) & 1);
            offB[p][kc] = swz((uint32_t)(n * ROWB + ch * 16));
        }

    load_stage(0, 0);
    load_stage(1, 1);

    for (int kt = 0; kt < K_TILES; ++kt) {
        const int s = kt % STAGES;
        if (kt + 2 < K_TILES) {
            asm volatile("cp.async.wait_group %0;" :: "n"(1) : "memory");
        } else {
            asm volatile("cp.async.wait_group %0;" :: "n"(0) : "memory");
        }
        __syncthreads();
        if (kt + 2 < K_TILES) load_stage((kt + 2) % STAGES, kt + 2);

        const uint32_t aBase = sA0 + s * STG_A;
        const uint32_t bBase = sB0 + s * STG_B;
#pragma unroll
        for (int kc = 0; kc < 2; ++kc) {
            uint32_t a[2][4];
            ldmx4(a[0], aBase + offA[0][kc]);
            ldmx4(a[1], aBase + offA[1][kc]);
#pragma unroll
            for (int p = 0; p < 8; ++p) {
                uint32_t b[4];  // R0=(n0-7,k0-7) R1=(n0-7,k8-15) R2=(n8-15,k0-7) R3=(n8-15,k8-15)
                ldmx4(b, bBase + offB[p][kc]);
                hmma(acc[0][2 * p + 0], a[0], b[0], b[1]);
                hmma(acc[1][2 * p + 0], a[1], b[0], b[1]);
                hmma(acc[0][2 * p + 1], a[0], b[2], b[3]);
                hmma(acc[1][2 * p + 1], a[1], b[2], b[3]);
            }
        }
    }

    // epilogue: dequant + bias
    const float dq = (__uint_as_float(g_amax_bits[0]) * __uint_as_float(g_amax_bits[1]))
                     / (127.0f * 127.0f);
    const int g = lane >> 2, tig = lane & 3;
    const int rbase = row0 + wM * 32;
    const int cbase = col0 + wN * 128;
#pragma unroll
    for (int ma = 0; ma < 2; ++ma) {
#pragma unroll
        for (int nb = 0; nb < 16; ++nb) {
            int r = rbase + ma * 16 + g;
            int c = cbase + nb * 8 + tig * 2;
            float2 bv = *(const float2*)(bias + c);
            float2 v0, v1;
            v0.x = acc[ma][nb][0] * dq + bv.x;
            v0.y = acc[ma][nb][1] * dq + bv.y;
            v1.x = acc[ma][nb][2] * dq + bv.x;
            v1.y = acc[ma][nb][3] * dq + bv.y;
            *(float2*)(out + (size_t)r * M_DIM + c) = v0;
            *(float2*)(out + (size_t)(r + 8) * M_DIM + c) = v1;
        }
    }
}

// ---------------------------------------------------------------- launch
extern "C" void kernel_launch(void* const* d_in, const int* in_sizes, int n_in,
                              void* d_out, int out_size) {
    const float* x = (const float*)d_in[0];
    const float* w = (const float*)d_in[1];
    const float* bias = (const float*)d_in[2];
    float* out = (float*)d_out;

    __half* qxh;
    __half* qwh;
    cudaGetSymbolAddress((void**)&qxh, g_qxh);
    cudaGetSymbolAddress((void**)&qwh, g_qwh);

    const long long nx4 = (long long)N_DIM * K_DIM / 4;
    const long long nw4 = (long long)M_DIM * K_DIM / 4;

    init_kernel<<<1, 32>>>();
    amax_kernel<<<1024, 256>>>(x, nx4, 0);
    amax_kernel<<<1024, 256>>>(w, nw4, 1);
    quant_both_kernel<<<dim3(1024, 2), 256>>>(x, w);

    static int smem_set = 0;
    if (!smem_set) {
        cudaFuncSetAttribute(gemm_hmma, cudaFuncAttributeMaxDynamicSharedMemorySize,
                             SMEM_TOTAL);
        smem_set = 1;
    }
    dim3 grid(M_DIM / BN, N_DIM / BM);
    gemm_hmma<<<grid, THREADS, SMEM_TOTAL>>>(qxh, qwh, bias, out);
}

// round 12
// speedup vs baseline: 2.9462x; 1.2543x over previous
#include <cuda_runtime.h>
#include <cuda_fp16.h>
#include <cstdint>

#define N_DIM 8192
#define K_DIM 4096
#define M_DIM 4096

#define BM 128
#define BN 256
#define BKH 64                          // K halves per stage
#define ROWB 128                        // bytes per smem row (64 halves)
#define STAGES 3
#define K_TILES (K_DIM / BKH)           // 64
#define THREADS 256

#define STG_A (BM * ROWB)               // 16384 B
#define STG_B (BN * ROWB)               // 32768 B
#define SM_B_OFF (STAGES * STG_A)       // 49152
#define SMEM_TOTAL (STAGES * (STG_A + STG_B))  // 147456

// Scratch (device globals: no allocation allowed)
__device__ __half g_qxh[(size_t)N_DIM * K_DIM];
__device__ __half g_qwh[(size_t)M_DIM * K_DIM];
__device__ unsigned int g_amax_bits[2];

// ---------------------------------------------------------------- helpers
__device__ __forceinline__ uint32_t smem_u32(const void* p) {
    uint32_t a;
    asm("{ .reg .u64 t; cvta.to.shared.u64 t, %1; cvt.u32.u64 %0, t; }" : "=r"(a) : "l"(p));
    return a;
}
__device__ __forceinline__ uint32_t swz128(uint32_t off) {  // SW128 for 128B rows
    return off ^ ((off >> 3) & 0x70);
}
__device__ __forceinline__ void cp16(uint32_t dst, const void* src) {
    asm volatile("cp.async.cg.shared.global [%0], [%1], 16;" :: "r"(dst), "l"(src));
}
#define CP_COMMIT() asm volatile("cp.async.commit_group;" ::: "memory")

__device__ __forceinline__ void ldmx4(uint32_t* r, uint32_t addr) {
    asm volatile("ldmatrix.sync.aligned.m8n8.x4.shared.b16 {%0,%1,%2,%3}, [%4];"
                 : "=r"(r[0]), "=r"(r[1]), "=r"(r[2]), "=r"(r[3]) : "r"(addr));
}
__device__ __forceinline__ void hmma(float* c, const uint32_t* a, uint32_t b0, uint32_t b1) {
    asm volatile(
        "mma.sync.aligned.m16n8k16.row.col.f32.f16.f16.f32 "
        "{%0,%1,%2,%3}, {%4,%5,%6,%7}, {%8,%9}, {%0,%1,%2,%3};"
        : "+f"(c[0]), "+f"(c[1]), "+f"(c[2]), "+f"(c[3])
        : "r"(a[0]), "r"(a[1]), "r"(a[2]), "r"(a[3]), "r"(b0), "r"(b1));
}

// ---------------------------------------------------------------- preproc
__global__ void init_kernel() { g_amax_bits[0] = 0u; g_amax_bits[1] = 0u; }

__global__ void amax_kernel(const float* __restrict__ in, long long n4, int slot) {
    float m = 0.0f;
    long long i0 = (long long)blockIdx.x * blockDim.x + threadIdx.x;
    long long stride = (long long)gridDim.x * blockDim.x;
    const float4* in4 = (const float4*)in;
    for (long long i = i0; i < n4; i += stride) {
        float4 v = in4[i];
        m = fmaxf(m, fmaxf(fmaxf(fabsf(v.x), fabsf(v.y)),
                           fmaxf(fabsf(v.z), fabsf(v.w))));
    }
#pragma unroll
    for (int o = 16; o; o >>= 1) m = fmaxf(m, __shfl_xor_sync(0xffffffffu, m, o));
    __shared__ float sm[32];
    int lane = threadIdx.x & 31, wid = threadIdx.x >> 5;
    if (lane == 0) sm[wid] = m;
    __syncthreads();
    if (wid == 0) {
        m = (lane < (int)(blockDim.x >> 5)) ? sm[lane] : 0.0f;
#pragma unroll
        for (int o = 16; o; o >>= 1) m = fmaxf(m, __shfl_xor_sync(0xffffffffu, m, o));
        if (lane == 0) atomicMax(&g_amax_bits[slot], __float_as_uint(m));
    }
}

__global__ void quant_both_kernel(const float* __restrict__ x, const float* __restrict__ w) {
    const int which = blockIdx.y;
    const float* in = which ? w : x;
    __half* out = which ? g_qwh : g_qxh;
    const long long n4 = which ? (long long)M_DIM * K_DIM / 4
                               : (long long)N_DIM * K_DIM / 4;
    float amax = __uint_as_float(g_amax_bits[which]);
    float scale = 127.0f / amax;
    long long i0 = (long long)blockIdx.x * blockDim.x + threadIdx.x;
    long long stride = (long long)gridDim.x * blockDim.x;
    const float4* in4 = (const float4*)in;
    __half2* out2 = (__half2*)out;
    for (long long i = i0; i < n4; i += stride) {
        float4 v = in4[i];
        float q0 = (float)__float2int_rn(fminf(fmaxf(v.x * scale, -127.0f), 127.0f));
        float q1 = (float)__float2int_rn(fminf(fmaxf(v.y * scale, -127.0f), 127.0f));
        float q2 = (float)__float2int_rn(fminf(fmaxf(v.z * scale, -127.0f), 127.0f));
        float q3 = (float)__float2int_rn(fminf(fmaxf(v.w * scale, -127.0f), 127.0f));
        out2[2 * i + 0] = __floats2half2_rn(q0, q1);
        out2[2 * i + 1] = __floats2half2_rn(q2, q3);
    }
}

// ---------------------------------------------------------------- HMMA GEMM
// Block 128x256, BK=64 halves (128B rows, SW128). 8 warps in 2(M) x 4(N);
// warp tile 64x64: 4 matoms x 8 n8-atoms of m16n8k16, 4 k-atoms per kt.
__global__ __launch_bounds__(THREADS, 1)
void gemm_hmma(const __half* __restrict__ qx, const __half* __restrict__ qw,
               const float* __restrict__ bias, float* __restrict__ out) {
    extern __shared__ char smem[];
    const uint32_t sA0 = smem_u32(smem);
    const uint32_t sB0 = sA0 + SM_B_OFF;

    const int tid = threadIdx.x, wid = tid >> 5, lane = tid & 31;
    const int wM = wid & 1, wN = wid >> 1;      // 2 x 4 warp grid
    const int row0 = blockIdx.y * BM;           // N_DIM
    const int col0 = blockIdx.x * BN;           // M_DIM

    const char* aG = (const char*)(qx + (size_t)row0 * K_DIM);
    const char* bG = (const char*)(qw + (size_t)col0 * K_DIM);

    float acc[4][8][4];
#pragma unroll
    for (int i = 0; i < 4; ++i)
#pragma unroll
        for (int j = 0; j < 8; ++j)
#pragma unroll
            for (int k = 0; k < 4; ++k) acc[i][j][k] = 0.0f;

    // stage loader: A 128 rows x 8 chunks = 1024 cp16; B 256 x 8 = 2048 cp16
    auto load_stage = [&](int s, int kt) {
        const size_t kb = (size_t)kt * ROWB;    // byte offset along K
#pragma unroll
        for (int p = 0; p < 4; ++p) {
            int i = p * THREADS + tid;
            int r = i >> 3, c = i & 7;
            uint32_t so = swz128((uint32_t)(r * ROWB + c * 16));
            cp16(sA0 + s * STG_A + so, aG + (size_t)r * (K_DIM * 2) + kb + c * 16);
        }
#pragma unroll
        for (int p = 0; p < 8; ++p) {
            int i = p * THREADS + tid;
            int r = i >> 3, c = i & 7;
            uint32_t so = swz128((uint32_t)(r * ROWB + c * 16));
            cp16(sB0 + s * STG_B + so, bG + (size_t)r * (K_DIM * 2) + kb + c * 16);
        }
        CP_COMMIT();
    };

    // ldmatrix offsets.
    // A (matom ma, katom kc): row = wM*64 + ma*16 + (lane&15), chunk = kc*2 + (lane>>4)
    uint32_t offA[4][4];
#pragma unroll
    for (int ma = 0; ma < 4; ++ma)
#pragma unroll
        for (int kc = 0; kc < 4; ++kc) {
            int r = wM * 64 + ma * 16 + (lane & 15);
            int ch = kc * 2 + (lane >> 4);
            offA[ma][kc] = swz128((uint32_t)(r * ROWB + ch * 16));
        }
    // B (n16 block p, katom kc): n = wN*64 + p*16 + ((lane>>4)&1)*8 + (lane&7)
    //                            chunk = kc*2 + ((lane>>3)&1)
    uint32_t offB[4][4];
#pragma unroll
    for (int p = 0; p < 4; ++p)
#pragma unroll
        for (int kc = 0; kc < 4; ++kc) {
            int n = wN * 64 + p * 16 + ((lane >> 4) & 1) * 8 + (lane & 7);
            int ch = kc * 2 + ((lane >> 3) & 1);
            offB[p][kc] = swz128((uint32_t)(n * ROWB + ch * 16));
        }

    load_stage(0, 0);
    load_stage(1, 1);

    for (int kt = 0; kt < K_TILES; ++kt) {
        const int s = kt % STAGES;
        if (kt + 2 < K_TILES) {
            asm volatile("cp.async.wait_group %0;" :: "n"(1) : "memory");
        } else {
            asm volatile("cp.async.wait_group %0;" :: "n"(0) : "memory");
        }
        __syncthreads();
        if (kt + 2 < K_TILES) load_stage((kt + 2) % STAGES, kt + 2);

        const uint32_t aBase = sA0 + s * STG_A;
        const uint32_t bBase = sB0 + s * STG_B;
#pragma unroll
        for (int kc = 0; kc < 4; ++kc) {
            uint32_t a[4][4];
            ldmx4(a[0], aBase + offA[0][kc]);
            ldmx4(a[1], aBase + offA[1][kc]);
            ldmx4(a[2], aBase + offA[2][kc]);
            ldmx4(a[3], aBase + offA[3][kc]);
#pragma unroll
            for (int p = 0; p < 4; ++p) {
                uint32_t b[4];  // R0=(n0-7,k0-7) R1=(n0-7,k8-15) R2=(n8-15,k0-7) R3=(n8-15,k8-15)
                ldmx4(b, bBase + offB[p][kc]);
#pragma unroll
                for (int ma = 0; ma < 4; ++ma) {
                    hmma(acc[ma][2 * p + 0], a[ma], b[0], b[1]);
                    hmma(acc[ma][2 * p + 1], a[ma], b[2], b[3]);
                }
            }
        }
    }

    // epilogue: dequant + bias
    const float dq = (__uint_as_float(g_amax_bits[0]) * __uint_as_float(g_amax_bits[1]))
                     / (127.0f * 127.0f);
    const int g = lane >> 2, tig = lane & 3;
    const int rbase = row0 + wM * 64;
    const int cbase = col0 + wN * 64;
#pragma unroll
    for (int ma = 0; ma < 4; ++ma) {
#pragma unroll
        for (int nb = 0; nb < 8; ++nb) {
            int r = rbase + ma * 16 + g;
            int c = cbase + nb * 8 + tig * 2;
            float2 bv = *(const float2*)(bias + c);
            float2 v0, v1;
            v0.x = acc[ma][nb][0] * dq + bv.x;
            v0.y = acc[ma][nb][1] * dq + bv.y;
            v1.x = acc[ma][nb][2] * dq + bv.x;
            v1.y = acc[ma][nb][3] * dq + bv.y;
            *(float2*)(out + (size_t)r * M_DIM + c) = v0;
            *(float2*)(out + (size_t)(r + 8) * M_DIM + c) = v1;
        }
    }
}

// ---------------------------------------------------------------- launch
extern "C" void kernel_launch(void* const* d_in, const int* in_sizes, int n_in,
                              void* d_out, int out_size) {
    const float* x = (const float*)d_in[0];
    const float* w = (const float*)d_in[1];
    const float* bias = (const float*)d_in[2];
    float* out = (float*)d_out;

    __half* qxh;
    __half* qwh;
    cudaGetSymbolAddress((void**)&qxh, g_qxh);
    cudaGetSymbolAddress((void**)&qwh, g_qwh);

    const long long nx4 = (long long)N_DIM * K_DIM / 4;
    const long long nw4 = (long long)M_DIM * K_DIM / 4;

    init_kernel<<<1, 32>>>();
    amax_kernel<<<1024, 256>>>(x, nx4, 0);
    amax_kernel<<<1024, 256>>>(w, nw4, 1);
    quant_both_kernel<<<dim3(1024, 2), 256>>>(x, w);

    static int smem_set = 0;
    if (!smem_set) {
        cudaFuncSetAttribute(gemm_hmma, cudaFuncAttributeMaxDynamicSharedMemorySize,
                             SMEM_TOTAL);
        smem_set = 1;
    }
    dim3 grid(M_DIM / BN, N_DIM / BM);
    gemm_hmma<<<grid, THREADS, SMEM_TOTAL>>>(qxh, qwh, bias, out);
}